// round 16
// baseline (speedup 1.0000x reference)
#include <cuda_runtime.h>
#include <cuda_fp16.h>
#include <cstdint>
#include <cstddef>

#define B_  4
#define C_  256
#define CQ_ 32
#define N_  4096
#define JT  128             // j tile per CTA
#define IT  64              // i tile per pipeline step
#define NIT (N_ / IT)       // 64
#define NTHR 512            // 16 warps
#define KSCALE 0.09016844005556021f   // (1/16) * log2(e)

// ---------------- scratch (device globals: allocation-free) ----------------
__device__ __half d_f[(size_t)B_ * N_ * CQ_];
__device__ __half d_g[(size_t)B_ * N_ * CQ_];
__device__ __half d_v[(size_t)B_ * C_ * N_];     // [b][c][n] values
__device__ __half d_xt[(size_t)B_ * N_ * C_];    // [b][n][c] x transposed fp16
__device__ __half d_wq16[CQ_ * C_];
__device__ __half d_wk16[CQ_ * C_];
__device__ __half d_wv16[C_ * C_];

__device__ __forceinline__ void mma_f16(float* d, const uint32_t* a,
                                        const uint32_t* b) {
    asm volatile(
        "mma.sync.aligned.m16n8k16.row.col.f32.f16.f16.f32 "
        "{%0,%1,%2,%3}, {%4,%5,%6,%7}, {%8,%9}, {%0,%1,%2,%3};"
        : "+f"(d[0]), "+f"(d[1]), "+f"(d[2]), "+f"(d[3])
        : "r"(a[0]), "r"(a[1]), "r"(a[2]), "r"(a[3]), "r"(b[0]), "r"(b[1]));
}
__device__ __forceinline__ uint32_t packh2(float a, float b) {
    __half2 p = __floats2half2_rn(a, b);
    return *reinterpret_cast<uint32_t*>(&p);
}
__device__ __forceinline__ uint32_t ex2h2(uint32_t x) {
    uint32_t y;
    asm("ex2.approx.f16x2 %0, %1;" : "=r"(y) : "r"(x));
    return y;
}
__device__ __forceinline__ void cp16(uint32_t dst, const void* src) {
    asm volatile("cp.async.cg.shared.global [%0], [%1], 16;"
                 :: "r"(dst), "l"(src));
}
#define CP_COMMIT() asm volatile("cp.async.commit_group;" ::: "memory")
#define CP_WAIT0()  asm volatile("cp.async.wait_group 0;" ::: "memory")

// --------------------------- fused SMEM layout -----------------------------
// g:  [128 j][32 q], stride 80
// f:  2 x [64 i][32 q], stride 80
// V:  2 x [256 c][64 i], stride 144 (128B data + 16 pad; banks 0,16,..,112)
// P:  2 x [128 j][64 i] k-interleaved, stride 160 (128B data + 32 pad)
#define GSTR 80
#define VSTR 144
#define PSTR 160
#define FBUF 5120
#define VBUF 36864
#define PBUF 20480
#define OFF_G    0                       // 10240
#define OFF_F    10240                   // -> 20480
#define OFF_V    20480                   // -> 94208
#define OFF_P    94208                   // -> 135168
#define OFF_LRED 135168                  // 1024
#define OFF_RINV 136192                  // 512
#define SMEM_TOTAL 136704

// =================== kernel 0a: convert weights to fp16 ===================
__global__ void conv_w_kernel(const float* __restrict__ Wq,
                              const float* __restrict__ Wk,
                              const float* __restrict__ Wv) {
    int i = blockIdx.x * 256 + threadIdx.x;
    if (i < CQ_ * C_)              d_wq16[i] = __float2half(Wq[i]);
    else if (i < 2 * CQ_ * C_)     d_wk16[i - CQ_ * C_] = __float2half(Wk[i - CQ_ * C_]);
    else if (i < 2 * CQ_ * C_ + C_ * C_)
        d_wv16[i - 2 * CQ_ * C_] = __float2half(Wv[i - 2 * CQ_ * C_]);
}

// =============== kernel 0b: transpose+convert x -> xt fp16 ================
__global__ void transpose_x_kernel(const float* __restrict__ x) {
    const int b = blockIdx.z, c0 = blockIdx.y * 64, n0 = blockIdx.x * 64;
    __shared__ float ts[64][65];
    const int tid = threadIdx.x;
    const float* X = x + ((size_t)b * C_ + c0) * N_;

    int crow = tid >> 2, ng = (tid & 3) * 16;
    #pragma unroll
    for (int i = 0; i < 4; ++i) {
        float4 v = *reinterpret_cast<const float4*>(&X[(size_t)crow * N_ + n0 + ng + 4 * i]);
        ts[crow][ng + 4 * i + 0] = v.x;
        ts[crow][ng + 4 * i + 1] = v.y;
        ts[crow][ng + 4 * i + 2] = v.z;
        ts[crow][ng + 4 * i + 3] = v.w;
    }
    __syncthreads();
    int nrow = tid >> 2, cg = (tid & 3) * 16;
    #pragma unroll
    for (int k = 0; k < 4; ++k) {
        uint2 w2;
        w2.x = packh2(ts[cg + 4 * k + 0][nrow], ts[cg + 4 * k + 1][nrow]);
        w2.y = packh2(ts[cg + 4 * k + 2][nrow], ts[cg + 4 * k + 3][nrow]);
        *reinterpret_cast<uint2*>(
            &d_xt[((size_t)b * N_ + n0 + nrow) * C_ + c0 + cg + 4 * k]) = w2;
    }
}

// ============ kernel 1a: f AND g projection via mma (one kernel) ==========
#define WSTR 528
__global__ void __launch_bounds__(256) proj_fg_mma() {
    __shared__ char sm[44032];          // W0 @0 (16896), W1 @16896, xt @33792
    const int b  = blockIdx.y;
    const int n0 = blockIdx.x * 128;
    const int tid  = threadIdx.x;
    const int lane = tid & 31, warp = tid >> 5;
    const int lr = lane >> 2, lm = lane & 3;
    const int nw = (warp >> 1) * 32, qw = (warp & 1) * 16;

    #pragma unroll
    for (int it = 0; it < 8; ++it) {
        int id = tid + 256 * it;
        int w = id >> 10, row = (id >> 5) & 31, ch = id & 31;
        const __half* src = w ? d_wk16 : d_wq16;
        uint4 v = *reinterpret_cast<const uint4*>(&src[row * C_ + ch * 8]);
        *reinterpret_cast<uint4*>(sm + w * 16896 + row * WSTR + ch * 16) = v;
    }

    float fac[2][2][2][4];
    #pragma unroll
    for (int w = 0; w < 2; ++w)
        #pragma unroll
        for (int mi = 0; mi < 2; ++mi)
            #pragma unroll
            for (int qi = 0; qi < 2; ++qi)
                #pragma unroll
                for (int k = 0; k < 4; ++k) fac[w][mi][qi][k] = 0.f;

    for (int chunk = 0; chunk < 8; ++chunk) {
        __syncthreads();
        #pragma unroll
        for (int it = 0; it < 2; ++it) {
            int id = tid + 256 * it;
            int row = id >> 2, ch = id & 3;
            uint4 v = *reinterpret_cast<const uint4*>(
                &d_xt[((size_t)b * N_ + n0 + row) * C_ + chunk * 32 + ch * 8]);
            *reinterpret_cast<uint4*>(sm + 33792 + row * GSTR + ch * 16) = v;
        }
        __syncthreads();

        #pragma unroll
        for (int ks = 0; ks < 2; ++ks) {
            uint32_t ag[2][4];
            #pragma unroll
            for (int mi = 0; mi < 2; ++mi) {
                const char* aa = sm + 33792 + (nw + mi * 16 + lr) * GSTR
                                 + ks * 32 + lm * 4;
                ag[mi][0] = *(const uint32_t*)aa;
                ag[mi][1] = *(const uint32_t*)(aa + 8 * GSTR);
                ag[mi][2] = *(const uint32_t*)(aa + 16);
                ag[mi][3] = *(const uint32_t*)(aa + 8 * GSTR + 16);
            }
            #pragma unroll
            for (int w = 0; w < 2; ++w) {
                #pragma unroll
                for (int qi = 0; qi < 2; ++qi) {
                    uint32_t bf[2];
                    const char* ba = sm + w * 16896 + (qw + qi * 8 + lr) * WSTR
                                     + chunk * 64 + ks * 32 + lm * 4;
                    bf[0] = *(const uint32_t*)ba;
                    bf[1] = *(const uint32_t*)(ba + 16);
                    #pragma unroll
                    for (int mi = 0; mi < 2; ++mi)
                        mma_f16(fac[w][mi][qi], ag[mi], bf);
                }
            }
        }
    }

    #pragma unroll
    for (int w = 0; w < 2; ++w) {
        __half* Y = w ? d_g : d_f;
        #pragma unroll
        for (int mi = 0; mi < 2; ++mi) {
            #pragma unroll
            for (int qi = 0; qi < 2; ++qi) {
                const int n = n0 + nw + mi * 16 + lr;
                const int q = qw + qi * 8 + 2 * lm;
                *reinterpret_cast<uint32_t*>(&Y[((size_t)b * N_ + n) * CQ_ + q]) =
                    packh2(fac[w][mi][qi][0], fac[w][mi][qi][1]);
                *reinterpret_cast<uint32_t*>(&Y[((size_t)b * N_ + n + 8) * CQ_ + q]) =
                    packh2(fac[w][mi][qi][2], fac[w][mi][qi][3]);
            }
        }
    }
}

// =================== kernel 1b: v projection via mma ======================
__global__ void __launch_bounds__(256) proj_v_mma() {
    __shared__ char sm[20480];
    const int b  = blockIdx.z;
    const int m0 = blockIdx.y * 128;
    const int n0 = blockIdx.x * 128;
    const int tid  = threadIdx.x;
    const int lane = tid & 31, warp = tid >> 5;
    const int lr = lane >> 2, lm = lane & 3;
    const int ca = (warp >> 2) * 64, nq = (warp & 3) * 32;

    float oacc[4][4][4];
    #pragma unroll
    for (int m = 0; m < 4; ++m)
        #pragma unroll
        for (int n = 0; n < 4; ++n)
            #pragma unroll
            for (int k = 0; k < 4; ++k) oacc[m][n][k] = 0.f;

    for (int chunk = 0; chunk < 8; ++chunk) {
        __syncthreads();
        #pragma unroll
        for (int it = 0; it < 2; ++it) {
            int id = tid + 256 * it;
            int row = id >> 2, ch = id & 3;
            uint4 v = *reinterpret_cast<const uint4*>(
                &d_wv16[(m0 + row) * C_ + chunk * 32 + ch * 8]);
            *reinterpret_cast<uint4*>(sm + row * GSTR + ch * 16) = v;
        }
        #pragma unroll
        for (int it = 0; it < 2; ++it) {
            int id = tid + 256 * it;
            int row = id >> 2, ch = id & 3;
            uint4 v = *reinterpret_cast<const uint4*>(
                &d_xt[((size_t)b * N_ + n0 + row) * C_ + chunk * 32 + ch * 8]);
            *reinterpret_cast<uint4*>(sm + 10240 + row * GSTR + ch * 16) = v;
        }
        __syncthreads();

        #pragma unroll
        for (int ks = 0; ks < 2; ++ks) {
            uint32_t af[4][4];
            #pragma unroll
            for (int mi = 0; mi < 4; ++mi) {
                const char* aa = sm + (ca + mi * 16 + lr) * GSTR + ks * 32 + lm * 4;
                af[mi][0] = *(const uint32_t*)aa;
                af[mi][1] = *(const uint32_t*)(aa + 8 * GSTR);
                af[mi][2] = *(const uint32_t*)(aa + 16);
                af[mi][3] = *(const uint32_t*)(aa + 8 * GSTR + 16);
            }
            #pragma unroll
            for (int ni = 0; ni < 4; ++ni) {
                uint32_t bf[2];
                const char* ba = sm + 10240 + (nq + ni * 8 + lr) * GSTR
                                 + ks * 32 + lm * 4;
                bf[0] = *(const uint32_t*)ba;
                bf[1] = *(const uint32_t*)(ba + 16);
                #pragma unroll
                for (int mi = 0; mi < 4; ++mi)
                    mma_f16(oacc[mi][ni], af[mi], bf);
            }
        }
    }

    #pragma unroll
    for (int mi = 0; mi < 4; ++mi) {
        #pragma unroll
        for (int ni = 0; ni < 4; ++ni) {
            const int c = m0 + ca + mi * 16 + lr;
            const int n = n0 + nq + ni * 8 + 2 * lm;
            *reinterpret_cast<uint32_t*>(&d_v[((size_t)b * C_ + c) * N_ + n]) =
                packh2(oacc[mi][ni][0], oacc[mi][ni][1]);
            *reinterpret_cast<uint32_t*>(&d_v[((size_t)b * C_ + c + 8) * N_ + n]) =
                packh2(oacc[mi][ni][2], oacc[mi][ni][3]);
        }
    }
}

// ====== kernel 2: fused, A/B pipelined, ONE barrier per 64-i step =========
// Invariant at the top-of-loop barrier of iteration t:
//   P(t) written, V(t) resident (buf t%2), f(t+1) resident (buf (t+1)%2),
//   all cp.async drained.
// Body: A(t+1) -> P((t+1)%2) ; prefetch V(t+1), f(t+2) ; B(t) ; cp.wait.
// A(t+1) and B(t) touch disjoint buffers -> no intra-iteration barrier; a
// warp's A epilogue (MUFU/pack/STS) overlaps other warps' B HMMAs.
__global__ void __launch_bounds__(NTHR, 1)
fused_attn_mma(float* __restrict__ out) {
    extern __shared__ __align__(16) char smem[];
    const uint32_t sb = (uint32_t)__cvta_generic_to_shared(smem);
    const int b  = blockIdx.y;
    const int jb = blockIdx.x * JT;
    const int tid  = threadIdx.x;
    const int lane = tid & 31, warp = tid >> 5;
    const int lr = lane >> 2, lm = lane & 3;
    const int jw = (warp >> 1) * 16;    // phase-A j strip (2 warps share)
    const int ih = warp & 1;            // phase-A i half (0: 0-31, 1: 32-63)
    const int ca = (warp >> 2) * 64;    // phase-B c block
    const int jq = (warp & 3) * 32;     // phase-B j block

    const __half* fB = d_f + (size_t)b * N_ * CQ_;
    const __half* gB = d_g + (size_t)b * N_ * CQ_;
    const __half* vB = d_v + (size_t)b * C_ * N_;

    // ---- prologue: g (LDG/STS); f(0),f(1),V(0) via cp.async ----
    {
        int row = tid >> 2, ch = tid & 3;              // 512 x 16B
        uint4 w = *reinterpret_cast<const uint4*>(&gB[(size_t)(jb + row) * CQ_ + ch * 8]);
        *reinterpret_cast<uint4*>(smem + OFF_G + row * GSTR + ch * 16) = w;
    }
    {   // f(0)->buf0 (tid<256), f(1)->buf1 (tid>=256): 256 x 16B each
        int h = tid >> 8, id = tid & 255;
        int row = id >> 2, ch = id & 3;
        cp16(sb + OFF_F + h * FBUF + row * GSTR + ch * 16,
             &fB[(size_t)(h * IT + row) * CQ_ + ch * 8]);
    }
    #pragma unroll
    for (int it = 0; it < 4; ++it) {   // V(0): 2048 x 16B -> buf0
        int id = tid + NTHR * it;
        int row = id >> 3, ch = id & 7;
        cp16(sb + OFF_V + row * VSTR + ch * 16, &vB[(size_t)row * N_ + ch * 8]);
    }
    CP_COMMIT();

    float oacc[4][4][4];
    #pragma unroll
    for (int m = 0; m < 4; ++m)
        #pragma unroll
        for (int n = 0; n < 4; ++n)
            #pragma unroll
            for (int k = 0; k < 4; ++k) oacc[m][n][k] = 0.f;
    float lsum0 = 0.f, lsum1 = 0.f;

    CP_WAIT0();
    __syncthreads();                       // g, f(0), f(1), V(0) visible

    // hoist loop-invariant g fragments (A operand): ag_all[kk][4]
    uint32_t ag_all[2][4];
    #pragma unroll
    for (int kk = 0; kk < 2; ++kk) {
        const char* ga = smem + OFF_G + (jw + lr) * GSTR + kk * 32 + lm * 4;
        ag_all[kk][0] = *(const uint32_t*)ga;
        ag_all[kk][1] = *(const uint32_t*)(ga + 8 * GSTR);
        ag_all[kk][2] = *(const uint32_t*)(ga + 16);
        ag_all[kk][3] = *(const uint32_t*)(ga + 8 * GSTR + 16);
    }

    // ---- A(0): f buf0 -> P buf0 ----
    {
        float sacc[4][4] = {};
        #pragma unroll
        for (int kk = 0; kk < 2; ++kk)
            #pragma unroll
            for (int n = 0; n < 4; ++n) {
                uint32_t bf[2];
                const char* fa = smem + OFF_F + (ih * 32 + n * 8 + lr) * GSTR
                                 + kk * 32 + lm * 4;
                bf[0] = *(const uint32_t*)fa;
                bf[1] = *(const uint32_t*)(fa + 16);
                mma_f16(sacc[n], ag_all[kk], bf);
            }
        #pragma unroll
        for (int n = 0; n < 4; ++n) {
            const int po = (ih * 2 + (n >> 1)) * 32 + (2 * lm + (n & 1)) * 4;
            uint32_t p01 = ex2h2(packh2(sacc[n][0] * KSCALE, sacc[n][1] * KSCALE));
            uint32_t p23 = ex2h2(packh2(sacc[n][2] * KSCALE, sacc[n][3] * KSCALE));
            float2 f01 = __half22float2(*reinterpret_cast<__half2*>(&p01));
            float2 f23 = __half22float2(*reinterpret_cast<__half2*>(&p23));
            lsum0 += f01.x + f01.y;
            lsum1 += f23.x + f23.y;
            *(uint32_t*)(smem + OFF_P + (jw + lr) * PSTR + po)     = p01;
            *(uint32_t*)(smem + OFF_P + (jw + lr + 8) * PSTR + po) = p23;
        }
    }

    for (int t = 0; t < NIT; ++t) {
        const int cur = t & 1, nxt = cur ^ 1;
        __syncthreads();   // P(t),V(t),f(t+1) visible; stale bufs free

        // ---- A(t+1): f buf nxt -> P buf nxt ----
        if (t + 1 < NIT) {
            float sacc[4][4] = {};
            #pragma unroll
            for (int kk = 0; kk < 2; ++kk)
                #pragma unroll
                for (int n = 0; n < 4; ++n) {
                    uint32_t bf[2];
                    const char* fa = smem + OFF_F + nxt * FBUF
                                     + (ih * 32 + n * 8 + lr) * GSTR + kk * 32 + lm * 4;
                    bf[0] = *(const uint32_t*)fa;
                    bf[1] = *(const uint32_t*)(fa + 16);
                    mma_f16(sacc[n], ag_all[kk], bf);
                }
            #pragma unroll
            for (int n = 0; n < 4; ++n) {
                const int po = (ih * 2 + (n >> 1)) * 32 + (2 * lm + (n & 1)) * 4;
                uint32_t p01 = ex2h2(packh2(sacc[n][0] * KSCALE, sacc[n][1] * KSCALE));
                uint32_t p23 = ex2h2(packh2(sacc[n][2] * KSCALE, sacc[n][3] * KSCALE));
                float2 f01 = __half22float2(*reinterpret_cast<__half2*>(&p01));
                float2 f23 = __half22float2(*reinterpret_cast<__half2*>(&p23));
                lsum0 += f01.x + f01.y;
                lsum1 += f23.x + f23.y;
                *(uint32_t*)(smem + OFF_P + nxt * PBUF + (jw + lr) * PSTR + po)     = p01;
                *(uint32_t*)(smem + OFF_P + nxt * PBUF + (jw + lr + 8) * PSTR + po) = p23;
            }

            // ---- prefetch V(t+1) -> buf nxt, f(t+2) -> buf cur ----
            const int i0n = (t + 1) * IT;
            #pragma unroll
            for (int it2 = 0; it2 < 4; ++it2) {
                int id = tid + NTHR * it2;
                int row = id >> 3, ch = id & 7;
                cp16(sb + OFF_V + nxt * VBUF + row * VSTR + ch * 16,
                     &vB[(size_t)row * N_ + i0n + ch * 8]);
            }
            if (t + 2 < NIT && tid < 256) {
                int row = tid >> 2, ch = tid & 3;
                cp16(sb + OFF_F + cur * FBUF + row * GSTR + ch * 16,
                     &fB[(size_t)((t + 2) * IT + row) * CQ_ + ch * 8]);
            }
            CP_COMMIT();
        }

        // ---- B(t): O (64c x 32j) += V(t) * P(t)  [bufs cur] ----
        #pragma unroll
        for (int kk = 0; kk < 4; ++kk) {          // i chunks of 16
            uint32_t af[4][4];
            #pragma unroll
            for (int m = 0; m < 4; ++m) {
                const char* aa = smem + OFF_V + cur * VBUF + (ca + m * 16 + lr) * VSTR
                                 + kk * 32 + lm * 4;
                af[m][0] = *(const uint32_t*)aa;
                af[m][1] = *(const uint32_t*)(aa + 8 * VSTR);
                af[m][2] = *(const uint32_t*)(aa + 16);
                af[m][3] = *(const uint32_t*)(aa + 8 * VSTR + 16);
            }
            #pragma unroll
            for (int n = 0; n < 4; ++n) {
                uint2 bv = *(const uint2*)(smem + OFF_P + cur * PBUF
                                           + (jq + n * 8 + lr) * PSTR + kk * 32 + lm * 8);
                uint32_t bf[2] = { bv.x, bv.y };
                #pragma unroll
                for (int m = 0; m < 4; ++m)
                    mma_f16(oacc[m][n], af[m], bf);
            }
        }

        CP_WAIT0();                               // prefetch drained
    }

    // ---- row sums -> rinv ----
    lsum0 += __shfl_xor_sync(0xffffffffu, lsum0, 1);
    lsum0 += __shfl_xor_sync(0xffffffffu, lsum0, 2);
    lsum1 += __shfl_xor_sync(0xffffffffu, lsum1, 1);
    lsum1 += __shfl_xor_sync(0xffffffffu, lsum1, 2);
    __syncthreads();
    if (lm == 0) {
        float* lred = reinterpret_cast<float*>(smem + OFF_LRED);
        lred[warp * 16 + lr]     = lsum0;
        lred[warp * 16 + lr + 8] = lsum1;
    }
    __syncthreads();
    if (tid < 128) {
        const float* lred = reinterpret_cast<const float*>(smem + OFF_LRED);
        int s = tid >> 4, jl = tid & 15;
        reinterpret_cast<float*>(smem + OFF_RINV)[tid] =
            1.0f / (lred[(2 * s) * 16 + jl] + lred[(2 * s + 1) * 16 + jl]);
    }
    __syncthreads();
    const float* rinv = reinterpret_cast<const float*>(smem + OFF_RINV);

    // ---- write O ----
    #pragma unroll
    for (int m = 0; m < 4; ++m) {
        #pragma unroll
        for (int n = 0; n < 4; ++n) {
            const int c = ca + m * 16 + lr;
            const int j = jq + n * 8 + lm * 2;
            const float r0 = rinv[j], r1 = rinv[j + 1];
            float2 o0 = make_float2(oacc[m][n][0] * r0, oacc[m][n][1] * r1);
            float2 o1 = make_float2(oacc[m][n][2] * r0, oacc[m][n][3] * r1);
            *reinterpret_cast<float2*>(&out[((size_t)b * C_ + c) * N_ + jb + j])     = o0;
            *reinterpret_cast<float2*>(&out[((size_t)b * C_ + c + 8) * N_ + jb + j]) = o1;
        }
    }
}

// ---------------------------------------------------------------------------
extern "C" void kernel_launch(void* const* d_in, const int* in_sizes, int n_in,
                              void* d_out, int out_size) {
    (void)in_sizes; (void)n_in; (void)out_size;
    const float* x  = (const float*)d_in[0];
    const float* Wq = (const float*)d_in[1];
    const float* Wk = (const float*)d_in[2];
    const float* Wv = (const float*)d_in[3];
    float* out = (float*)d_out;

    static int smem_set = 0;
    if (!smem_set) {
        cudaFuncSetAttribute(fused_attn_mma,
                             cudaFuncAttributeMaxDynamicSharedMemorySize, SMEM_TOTAL);
        smem_set = 1;
    }

    conv_w_kernel<<<(2 * CQ_ * C_ + C_ * C_ + 255) / 256, 256>>>(Wq, Wk, Wv);
    transpose_x_kernel<<<dim3(N_ / 64, C_ / 64, B_), 256>>>(x);
    proj_fg_mma<<<dim3(N_ / 128, B_), 256>>>();
    proj_v_mma<<<dim3(N_ / 128, C_ / 128, B_), 256>>>();
    fused_attn_mma<<<dim3(N_ / JT, B_), NTHR, SMEM_TOTAL>>>(out);
}

// round 17
// speedup vs baseline: 1.0121x; 1.0121x over previous
#include <cuda_runtime.h>
#include <cuda_fp16.h>
#include <cstdint>
#include <cstddef>

#define B_  4
#define C_  256
#define CQ_ 32
#define N_  4096
#define JT  128             // j tile per CTA
#define IT  128             // i tile per mainloop step
#define NIT (N_ / IT)       // 32
#define NTHR 512            // 16 warps
#define KSCALE 0.09016844005556021f   // (1/16) * log2(e)

// ---------------- scratch (device globals: allocation-free) ----------------
__device__ __half d_f[(size_t)B_ * N_ * CQ_];
__device__ __half d_g[(size_t)B_ * N_ * CQ_];
__device__ __half d_v[(size_t)B_ * C_ * N_];     // [b][c][n] values
__device__ __half d_xt[(size_t)B_ * N_ * C_];    // [b][n][c] x transposed fp16
__device__ __half d_wq16[CQ_ * C_];
__device__ __half d_wk16[CQ_ * C_];
__device__ __half d_wv16[C_ * C_];

__device__ __forceinline__ void mma_f16(float* d, const uint32_t* a,
                                        const uint32_t* b) {
    asm volatile(
        "mma.sync.aligned.m16n8k16.row.col.f32.f16.f16.f32 "
        "{%0,%1,%2,%3}, {%4,%5,%6,%7}, {%8,%9}, {%0,%1,%2,%3};"
        : "+f"(d[0]), "+f"(d[1]), "+f"(d[2]), "+f"(d[3])
        : "r"(a[0]), "r"(a[1]), "r"(a[2]), "r"(a[3]), "r"(b[0]), "r"(b[1]));
}
__device__ __forceinline__ uint32_t packh2(float a, float b) {
    __half2 p = __floats2half2_rn(a, b);
    return *reinterpret_cast<uint32_t*>(&p);
}
__device__ __forceinline__ uint32_t ex2h2(uint32_t x) {
    uint32_t y;
    asm("ex2.approx.f16x2 %0, %1;" : "=r"(y) : "r"(x));
    return y;
}
__device__ __forceinline__ void cp16(uint32_t dst, const void* src) {
    asm volatile("cp.async.cg.shared.global [%0], [%1], 16;"
                 :: "r"(dst), "l"(src));
}
#define CP_COMMIT() asm volatile("cp.async.commit_group;" ::: "memory")
#define CP_WAIT0()  asm volatile("cp.async.wait_group 0;" ::: "memory")
#define CP_WAIT1()  asm volatile("cp.async.wait_group 1;" ::: "memory")

// --------------------------- fused SMEM layout (R15 winner) ----------------
#define GSTR 80
#define VSTR 272
#define PSTR 288
#define FBUF 10240
#define VBUF 69632
#define OFF_G    0                       // 10240
#define OFF_F    10240                   // 2 x 10240 -> 30720
#define OFF_V    30720                   // 2 x 69632 -> 169984
#define OFF_P    169984                  // 128*288 = 36864 -> 206848
#define OFF_LRED 206848                  // 1024
#define OFF_RINV 207872                  // 512
#define SMEM_TOTAL 208384

// =================== kernel 0a: convert weights to fp16 ===================
__global__ void conv_w_kernel(const float* __restrict__ Wq,
                              const float* __restrict__ Wk,
                              const float* __restrict__ Wv) {
    int i = blockIdx.x * 256 + threadIdx.x;
    if (i < CQ_ * C_)              d_wq16[i] = __float2half(Wq[i]);
    else if (i < 2 * CQ_ * C_)     d_wk16[i - CQ_ * C_] = __float2half(Wk[i - CQ_ * C_]);
    else if (i < 2 * CQ_ * C_ + C_ * C_)
        d_wv16[i - 2 * CQ_ * C_] = __float2half(Wv[i - 2 * CQ_ * C_]);
}

// =============== kernel 0b: transpose+convert x -> xt fp16 ================
__global__ void transpose_x_kernel(const float* __restrict__ x) {
    const int b = blockIdx.z, c0 = blockIdx.y * 64, n0 = blockIdx.x * 64;
    __shared__ float ts[64][65];
    const int tid = threadIdx.x;
    const float* X = x + ((size_t)b * C_ + c0) * N_;

    int crow = tid >> 2, ng = (tid & 3) * 16;
    #pragma unroll
    for (int i = 0; i < 4; ++i) {
        float4 v = *reinterpret_cast<const float4*>(&X[(size_t)crow * N_ + n0 + ng + 4 * i]);
        ts[crow][ng + 4 * i + 0] = v.x;
        ts[crow][ng + 4 * i + 1] = v.y;
        ts[crow][ng + 4 * i + 2] = v.z;
        ts[crow][ng + 4 * i + 3] = v.w;
    }
    __syncthreads();
    int nrow = tid >> 2, cg = (tid & 3) * 16;
    #pragma unroll
    for (int k = 0; k < 4; ++k) {
        uint2 w2;
        w2.x = packh2(ts[cg + 4 * k + 0][nrow], ts[cg + 4 * k + 1][nrow]);
        w2.y = packh2(ts[cg + 4 * k + 2][nrow], ts[cg + 4 * k + 3][nrow]);
        *reinterpret_cast<uint2*>(
            &d_xt[((size_t)b * N_ + n0 + nrow) * C_ + c0 + cg + 4 * k]) = w2;
    }
}

// ============ kernel 1a: f AND g projection via mma (one kernel) ==========
#define WSTR 528
__global__ void __launch_bounds__(256) proj_fg_mma() {
    __shared__ char sm[44032];          // W0 @0 (16896), W1 @16896, xt @33792
    const int b  = blockIdx.y;
    const int n0 = blockIdx.x * 128;
    const int tid  = threadIdx.x;
    const int lane = tid & 31, warp = tid >> 5;
    const int lr = lane >> 2, lm = lane & 3;
    const int nw = (warp >> 1) * 32, qw = (warp & 1) * 16;

    #pragma unroll
    for (int it = 0; it < 8; ++it) {
        int id = tid + 256 * it;
        int w = id >> 10, row = (id >> 5) & 31, ch = id & 31;
        const __half* src = w ? d_wk16 : d_wq16;
        uint4 v = *reinterpret_cast<const uint4*>(&src[row * C_ + ch * 8]);
        *reinterpret_cast<uint4*>(sm + w * 16896 + row * WSTR + ch * 16) = v;
    }

    float fac[2][2][2][4];
    #pragma unroll
    for (int w = 0; w < 2; ++w)
        #pragma unroll
        for (int mi = 0; mi < 2; ++mi)
            #pragma unroll
            for (int qi = 0; qi < 2; ++qi)
                #pragma unroll
                for (int k = 0; k < 4; ++k) fac[w][mi][qi][k] = 0.f;

    for (int chunk = 0; chunk < 8; ++chunk) {
        __syncthreads();
        #pragma unroll
        for (int it = 0; it < 2; ++it) {
            int id = tid + 256 * it;
            int row = id >> 2, ch = id & 3;
            uint4 v = *reinterpret_cast<const uint4*>(
                &d_xt[((size_t)b * N_ + n0 + row) * C_ + chunk * 32 + ch * 8]);
            *reinterpret_cast<uint4*>(sm + 33792 + row * GSTR + ch * 16) = v;
        }
        __syncthreads();

        #pragma unroll
        for (int ks = 0; ks < 2; ++ks) {
            uint32_t ag[2][4];
            #pragma unroll
            for (int mi = 0; mi < 2; ++mi) {
                const char* aa = sm + 33792 + (nw + mi * 16 + lr) * GSTR
                                 + ks * 32 + lm * 4;
                ag[mi][0] = *(const uint32_t*)aa;
                ag[mi][1] = *(const uint32_t*)(aa + 8 * GSTR);
                ag[mi][2] = *(const uint32_t*)(aa + 16);
                ag[mi][3] = *(const uint32_t*)(aa + 8 * GSTR + 16);
            }
            #pragma unroll
            for (int w = 0; w < 2; ++w) {
                #pragma unroll
                for (int qi = 0; qi < 2; ++qi) {
                    uint32_t bf[2];
                    const char* ba = sm + w * 16896 + (qw + qi * 8 + lr) * WSTR
                                     + chunk * 64 + ks * 32 + lm * 4;
                    bf[0] = *(const uint32_t*)ba;
                    bf[1] = *(const uint32_t*)(ba + 16);
                    #pragma unroll
                    for (int mi = 0; mi < 2; ++mi)
                        mma_f16(fac[w][mi][qi], ag[mi], bf);
                }
            }
        }
    }

    #pragma unroll
    for (int w = 0; w < 2; ++w) {
        __half* Y = w ? d_g : d_f;
        #pragma unroll
        for (int mi = 0; mi < 2; ++mi) {
            #pragma unroll
            for (int qi = 0; qi < 2; ++qi) {
                const int n = n0 + nw + mi * 16 + lr;
                const int q = qw + qi * 8 + 2 * lm;
                *reinterpret_cast<uint32_t*>(&Y[((size_t)b * N_ + n) * CQ_ + q]) =
                    packh2(fac[w][mi][qi][0], fac[w][mi][qi][1]);
                *reinterpret_cast<uint32_t*>(&Y[((size_t)b * N_ + n + 8) * CQ_ + q]) =
                    packh2(fac[w][mi][qi][2], fac[w][mi][qi][3]);
            }
        }
    }
}

// ======= kernel 1b v2: v projection, single wave + cp.async pipeline ======
// CTA: 128 c x 256 n (grid 16 x 2 x 4 = 128 CTAs = one full wave).
// 16 warps, 512 threads; warp tile 64c x 32n (ca = (warp>>3)*64, nq=(warp&7)*32).
// K = 256 in 8 chunks of 32, double-buffered via cp.async:
//   chunk buf = 30720 B (Wv [128][32] @ +0, xt [256][32] @ +10240), x2.
#define PV_BUF   30720
#define PV_XT    10240
#define PV_SMEM  61440
__global__ void __launch_bounds__(512) proj_v_mma() {
    extern __shared__ char smv[];
    const uint32_t sbv = (uint32_t)__cvta_generic_to_shared(smv);
    const int b  = blockIdx.z;
    const int m0 = blockIdx.y * 128;
    const int n0 = blockIdx.x * 256;
    const int tid  = threadIdx.x;
    const int lane = tid & 31, warp = tid >> 5;
    const int lr = lane >> 2, lm = lane & 3;
    const int ca = (warp >> 3) * 64, nq = (warp & 7) * 32;

    // ---- issue chunk 0 -> buf 0 ----
    {
        int row = tid >> 2, ch = tid & 3;      // Wv: 128 rows x 64B (512 ops)
        cp16(sbv + row * GSTR + ch * 16,
             &d_wv16[(m0 + row) * C_ + ch * 8]);
        #pragma unroll
        for (int it = 0; it < 2; ++it) {       // xt: 256 rows x 64B (1024 ops)
            int id = tid + 512 * it;
            int r2 = id >> 2, c2 = id & 3;
            cp16(sbv + PV_XT + r2 * GSTR + c2 * 16,
                 &d_xt[((size_t)b * N_ + n0 + r2) * C_ + c2 * 8]);
        }
        CP_COMMIT();
    }

    float oacc[4][4][4];
    #pragma unroll
    for (int m = 0; m < 4; ++m)
        #pragma unroll
        for (int n = 0; n < 4; ++n)
            #pragma unroll
            for (int k = 0; k < 4; ++k) oacc[m][n][k] = 0.f;

    for (int chunk = 0; chunk < 8; ++chunk) {
        const int cur = chunk & 1, nxt = cur ^ 1;
        // issue chunk+1 -> buf nxt
        if (chunk + 1 < 8) {
            int row = tid >> 2, ch = tid & 3;
            cp16(sbv + nxt * PV_BUF + row * GSTR + ch * 16,
                 &d_wv16[(m0 + row) * C_ + (chunk + 1) * 32 + ch * 8]);
            #pragma unroll
            for (int it = 0; it < 2; ++it) {
                int id = tid + 512 * it;
                int r2 = id >> 2, c2 = id & 3;
                cp16(sbv + nxt * PV_BUF + PV_XT + r2 * GSTR + c2 * 16,
                     &d_xt[((size_t)b * N_ + n0 + r2) * C_ + (chunk + 1) * 32 + c2 * 8]);
            }
            CP_COMMIT();
            CP_WAIT1();                        // chunk `chunk` landed
        } else {
            CP_WAIT0();
        }
        __syncthreads();                       // visible to all warps

        const char* wv = smv + cur * PV_BUF;
        const char* xt = smv + cur * PV_BUF + PV_XT;
        #pragma unroll
        for (int ks = 0; ks < 2; ++ks) {
            uint32_t af[4][4];
            #pragma unroll
            for (int mi = 0; mi < 4; ++mi) {
                const char* aa = wv + (ca + mi * 16 + lr) * GSTR + ks * 32 + lm * 4;
                af[mi][0] = *(const uint32_t*)aa;
                af[mi][1] = *(const uint32_t*)(aa + 8 * GSTR);
                af[mi][2] = *(const uint32_t*)(aa + 16);
                af[mi][3] = *(const uint32_t*)(aa + 8 * GSTR + 16);
            }
            #pragma unroll
            for (int ni = 0; ni < 4; ++ni) {
                uint32_t bf[2];
                const char* ba = xt + (nq + ni * 8 + lr) * GSTR + ks * 32 + lm * 4;
                bf[0] = *(const uint32_t*)ba;
                bf[1] = *(const uint32_t*)(ba + 16);
                #pragma unroll
                for (int mi = 0; mi < 4; ++mi)
                    mma_f16(oacc[mi][ni], af[mi], bf);
            }
        }
        __syncthreads();                       // compute done before buf reuse
    }

    #pragma unroll
    for (int mi = 0; mi < 4; ++mi) {
        #pragma unroll
        for (int ni = 0; ni < 4; ++ni) {
            const int c = m0 + ca + mi * 16 + lr;
            const int n = n0 + nq + ni * 8 + 2 * lm;
            *reinterpret_cast<uint32_t*>(&d_v[((size_t)b * C_ + c) * N_ + n]) =
                packh2(oacc[mi][ni][0], oacc[mi][ni][1]);
            *reinterpret_cast<uint32_t*>(&d_v[((size_t)b * C_ + c + 8) * N_ + n]) =
                packh2(oacc[mi][ni][2], oacc[mi][ni][3]);
        }
    }
}

// ============ kernel 2: fused (R15 winner, byte-for-byte) =================
__global__ void __launch_bounds__(NTHR, 1)
fused_attn_mma(float* __restrict__ out) {
    extern __shared__ __align__(16) char smem[];
    const uint32_t sb = (uint32_t)__cvta_generic_to_shared(smem);
    const int b  = blockIdx.y;
    const int jb = blockIdx.x * JT;
    const int tid  = threadIdx.x;
    const int lane = tid & 31, warp = tid >> 5;
    const int lr = lane >> 2, lm = lane & 3;
    const int jw = (warp >> 1) * 16;    // phase-A j strip (2 warps share)
    const int ih = warp & 1;            // phase-A i half (0: 0-63, 1: 64-127)
    const int ca = (warp >> 2) * 64;    // phase-B c block
    const int jq = (warp & 3) * 32;     // phase-B j block

    const __half* fB = d_f + (size_t)b * N_ * CQ_;
    const __half* gB = d_g + (size_t)b * N_ * CQ_;
    const __half* vB = d_v + (size_t)b * C_ * N_;

    // ---- prologue: g (LDG/STS), f(0) + V(0) via cp.async ----
    const int grow = tid >> 2, gch = tid & 3;          // 512 x 16B
    {
        uint4 w = *reinterpret_cast<const uint4*>(&gB[(size_t)(jb + grow) * CQ_ + gch * 8]);
        *reinterpret_cast<uint4*>(smem + OFF_G + grow * GSTR + gch * 16) = w;
    }
    cp16(sb + OFF_F + grow * GSTR + gch * 16, &fB[(size_t)grow * CQ_ + gch * 8]);
    #pragma unroll
    for (int it = 0; it < 8; ++it) {
        int id = tid + NTHR * it;
        int row = id >> 4, ch = id & 15;
        cp16(sb + OFF_V + row * VSTR + ch * 16, &vB[(size_t)row * N_ + ch * 8]);
    }
    CP_COMMIT();

    float oacc[4][4][4];
    #pragma unroll
    for (int m = 0; m < 4; ++m)
        #pragma unroll
        for (int n = 0; n < 4; ++n)
            #pragma unroll
            for (int k = 0; k < 4; ++k) oacc[m][n][k] = 0.f;
    float lsum0 = 0.f, lsum1 = 0.f;

    CP_WAIT0();
    __syncthreads();                       // prologue tiles visible

    for (int t = 0; t < NIT; ++t) {
        const int cur = t & 1, nxt = cur ^ 1;

        // ---------------- phase A(t): S strip (16 j x 64 i) + exp -> P ----
        {
            float sacc[8][4] = {};
            #pragma unroll
            for (int kk = 0; kk < 2; ++kk) {      // q chunks of 16
                uint32_t ag[4];
                const char* ga = smem + OFF_G + (jw + lr) * GSTR + kk * 32 + lm * 4;
                ag[0] = *(const uint32_t*)ga;
                ag[1] = *(const uint32_t*)(ga + 8 * GSTR);
                ag[2] = *(const uint32_t*)(ga + 16);
                ag[3] = *(const uint32_t*)(ga + 8 * GSTR + 16);
                #pragma unroll
                for (int n = 0; n < 8; ++n) {
                    uint32_t bf[2];
                    const char* fa = smem + OFF_F + cur * FBUF
                                     + (ih * 64 + n * 8 + lr) * GSTR + kk * 32 + lm * 4;
                    bf[0] = *(const uint32_t*)fa;
                    bf[1] = *(const uint32_t*)(fa + 16);
                    mma_f16(sacc[n], ag, bf);
                }
            }
            #pragma unroll
            for (int n = 0; n < 8; ++n) {
                const int po = (ih * 4 + (n >> 1)) * 32 + (2 * lm + (n & 1)) * 4;
                uint32_t p01 = ex2h2(packh2(sacc[n][0] * KSCALE, sacc[n][1] * KSCALE));
                uint32_t p23 = ex2h2(packh2(sacc[n][2] * KSCALE, sacc[n][3] * KSCALE));
                float2 f01 = __half22float2(*reinterpret_cast<__half2*>(&p01));
                float2 f23 = __half22float2(*reinterpret_cast<__half2*>(&p23));
                lsum0 += f01.x + f01.y;
                lsum1 += f23.x + f23.y;
                *(uint32_t*)(smem + OFF_P + (jw + lr) * PSTR + po)     = p01;
                *(uint32_t*)(smem + OFF_P + (jw + lr + 8) * PSTR + po) = p23;
            }
        }

        // ---- prefetch f(t+1), V(t+1) into bufs nxt (lands during B) ----
        if (t + 1 < NIT) {
            const int i0n = (t + 1) * IT;
            cp16(sb + OFF_F + nxt * FBUF + grow * GSTR + gch * 16,
                 &fB[(size_t)(i0n + grow) * CQ_ + gch * 8]);
            #pragma unroll
            for (int it = 0; it < 8; ++it) {
                int id = tid + NTHR * it;
                int row = id >> 4, ch = id & 15;
                cp16(sb + OFF_V + nxt * VBUF + row * VSTR + ch * 16,
                     &vB[(size_t)row * N_ + i0n + ch * 8]);
            }
            CP_COMMIT();
        }
        __syncthreads();                          // P visible

        // ---------------- phase B(t): O (64 c x 32 j) += V * P ------------
        #pragma unroll
        for (int kk = 0; kk < 8; ++kk) {          // i chunks of 16
            uint32_t af[4][4];
            #pragma unroll
            for (int m = 0; m < 4; ++m) {
                const char* aa = smem + OFF_V + cur * VBUF + (ca + m * 16 + lr) * VSTR
                                 + kk * 32 + lm * 4;
                af[m][0] = *(const uint32_t*)aa;
                af[m][1] = *(const uint32_t*)(aa + 8 * VSTR);
                af[m][2] = *(const uint32_t*)(aa + 16);
                af[m][3] = *(const uint32_t*)(aa + 8 * VSTR + 16);
            }
            #pragma unroll
            for (int n = 0; n < 4; ++n) {
                uint2 bv = *(const uint2*)(smem + OFF_P + (jq + n * 8 + lr) * PSTR
                                           + kk * 32 + lm * 8);
                uint32_t bf[2] = { bv.x, bv.y };
                #pragma unroll
                for (int m = 0; m < 4; ++m)
                    mma_f16(oacc[m][n], af[m], bf);
            }
        }

        CP_WAIT0();                               // prefetch landed (per-thread)
        __syncthreads();                          // visible to all; P/V(cur) free
    }

    // ---- row sums -> rinv ----
    lsum0 += __shfl_xor_sync(0xffffffffu, lsum0, 1);
    lsum0 += __shfl_xor_sync(0xffffffffu, lsum0, 2);
    lsum1 += __shfl_xor_sync(0xffffffffu, lsum1, 1);
    lsum1 += __shfl_xor_sync(0xffffffffu, lsum1, 2);
    if (lm == 0) {
        float* lred = reinterpret_cast<float*>(smem + OFF_LRED);
        lred[warp * 16 + lr]     = lsum0;
        lred[warp * 16 + lr + 8] = lsum1;
    }
    __syncthreads();
    if (tid < 128) {
        const float* lred = reinterpret_cast<const float*>(smem + OFF_LRED);
        int s = tid >> 4, jl = tid & 15;
        reinterpret_cast<float*>(smem + OFF_RINV)[tid] =
            1.0f / (lred[(2 * s) * 16 + jl] + lred[(2 * s + 1) * 16 + jl]);
    }
    __syncthreads();
    const float* rinv = reinterpret_cast<const float*>(smem + OFF_RINV);

    // ---- write O ----
    #pragma unroll
    for (int m = 0; m < 4; ++m) {
        #pragma unroll
        for (int n = 0; n < 4; ++n) {
            const int c = ca + m * 16 + lr;
            const int j = jq + n * 8 + lm * 2;
            const float r0 = rinv[j], r1 = rinv[j + 1];
            float2 o0 = make_float2(oacc[m][n][0] * r0, oacc[m][n][1] * r1);
            float2 o1 = make_float2(oacc[m][n][2] * r0, oacc[m][n][3] * r1);
            *reinterpret_cast<float2*>(&out[((size_t)b * C_ + c) * N_ + jb + j])     = o0;
            *reinterpret_cast<float2*>(&out[((size_t)b * C_ + c + 8) * N_ + jb + j]) = o1;
        }
    }
}

// ---------------------------------------------------------------------------
extern "C" void kernel_launch(void* const* d_in, const int* in_sizes, int n_in,
                              void* d_out, int out_size) {
    (void)in_sizes; (void)n_in; (void)out_size;
    const float* x  = (const float*)d_in[0];
    const float* Wq = (const float*)d_in[1];
    const float* Wk = (const float*)d_in[2];
    const float* Wv = (const float*)d_in[3];
    float* out = (float*)d_out;

    static int smem_set = 0;
    if (!smem_set) {
        cudaFuncSetAttribute(fused_attn_mma,
                             cudaFuncAttributeMaxDynamicSharedMemorySize, SMEM_TOTAL);
        cudaFuncSetAttribute(proj_v_mma,
                             cudaFuncAttributeMaxDynamicSharedMemorySize, PV_SMEM);
        smem_set = 1;
    }

    conv_w_kernel<<<(2 * CQ_ * C_ + C_ * C_ + 255) / 256, 256>>>(Wq, Wk, Wv);
    transpose_x_kernel<<<dim3(N_ / 64, C_ / 64, B_), 256>>>(x);
    proj_fg_mma<<<dim3(N_ / 128, B_), 256>>>();
    proj_v_mma<<<dim3(N_ / 256, C_ / 128, B_), 512, PV_SMEM>>>();
    fused_attn_mma<<<dim3(N_ / JT, B_), NTHR, SMEM_TOTAL>>>(out);
}